// round 12
// baseline (speedup 1.0000x reference)
#include <cuda_runtime.h>
#include <math.h>

#define B_  256
#define T_  100
#define F_  1024
#define H1_ 512
#define H2_ 512
#define O_  10
#define KW  128          // u32 words per 512-int8 row

// ---------------- device scratch ----------------
__device__ float d_Wq1[H1_ * F_];                 // dequantized fp32 W1
__device__ unsigned d_W2P[H2_ * KW];              // packed int8 q
__device__ unsigned d_WiP[H2_ * KW];
__device__ unsigned d_WoP[H2_ * KW];
__device__ unsigned d_W3P[O_ * KW];               // 1280 words
__device__ float d_cur1[(size_t)T_ * B_ * H1_];   // [b*T+t, h1]
__device__ unsigned d_s1P[B_ * KW];               // spikes packed as bytes
__device__ unsigned d_bsP[B_ * KW];
__device__ unsigned d_rspkP[B_ * KW];
__device__ float d_scales[5];

// ---------------- asm wrappers ----------------
__device__ __forceinline__ unsigned smem_u32(const void* p) {
    return (unsigned)__cvta_generic_to_shared(p);
}
__device__ __forceinline__ void ldmA(unsigned (&a)[4], unsigned addr) {
    asm volatile("ldmatrix.sync.aligned.m8n8.x4.shared.b16 {%0,%1,%2,%3}, [%4];"
                 : "=r"(a[0]), "=r"(a[1]), "=r"(a[2]), "=r"(a[3]) : "r"(addr));
}
__device__ __forceinline__ void ldmB(unsigned (&b)[2], unsigned addr) {
    asm volatile("ldmatrix.sync.aligned.m8n8.x2.shared.b16 {%0,%1}, [%2];"
                 : "=r"(b[0]), "=r"(b[1]) : "r"(addr));
}
__device__ __forceinline__ void mma_s8(int (&c)[4], const unsigned (&a)[4], const unsigned (&b)[2]) {
    asm volatile("mma.sync.aligned.m16n8k32.row.col.s32.s8.s8.s32 "
                 "{%0,%1,%2,%3},{%4,%5,%6,%7},{%8,%9},{%0,%1,%2,%3};"
                 : "+r"(c[0]), "+r"(c[1]), "+r"(c[2]), "+r"(c[3])
                 : "r"(a[0]), "r"(a[1]), "r"(a[2]), "r"(a[3]), "r"(b[0]), "r"(b[1]));
}
// packed fp32x2 FMA (per-lane IEEE fp32 fma; proven rel_err-neutral in R4/R6)
__device__ __forceinline__ void ffma2(unsigned long long &c, unsigned long long a, unsigned long long b) {
    asm("fma.rn.f32x2 %0, %1, %2, %0;" : "+l"(c) : "l"(a), "l"(b));
}
__device__ __forceinline__ unsigned long long pk2(float x, float y) {
    unsigned long long r;
    asm("mov.b64 %0, {%1, %2};" : "=l"(r) : "f"(x), "f"(y));
    return r;
}
__device__ __forceinline__ void upk2(float &x, float &y, unsigned long long v) {
    asm("mov.b64 {%0, %1}, %2;" : "=f"(x), "=f"(y) : "l"(v));
}
#define CLUSYNC() do { \
    asm volatile("barrier.cluster.arrive.aligned;" ::: "memory"); \
    asm volatile("barrier.cluster.wait.aligned;"   ::: "memory"); \
} while (0)

// ---------------- init ----------------
__global__ void init_kernel() {
    int i = blockIdx.x * blockDim.x + threadIdx.x;
    if (i < B_ * KW) d_rspkP[i] = 0u;
    if (i < 5) d_scales[i] = 0.f;
}

// ---------------- max|w| for all 5 matrices, one launch ----------------
__global__ void maxabs_all(const float* __restrict__ W1, const float* __restrict__ W2,
                           const float* __restrict__ Wi, const float* __restrict__ Wo,
                           const float* __restrict__ W3) {
    __shared__ float red[256];
    int slot = blockIdx.y;
    const float* w; int n;
    switch (slot) {
        case 0: w = W1; n = H1_ * F_;  break;
        case 1: w = W2; n = H2_ * H1_; break;
        case 2: w = Wi; n = H2_ * H2_; break;
        case 3: w = Wo; n = H2_ * H2_; break;
        default: w = W3; n = O_ * H2_; break;
    }
    float m = 0.f;
    for (int i = blockIdx.x * blockDim.x + threadIdx.x; i < n; i += gridDim.x * blockDim.x)
        m = fmaxf(m, fabsf(w[i]));
    red[threadIdx.x] = m;
    __syncthreads();
    for (int s = 128; s > 0; s >>= 1) {
        if (threadIdx.x < s) red[threadIdx.x] = fmaxf(red[threadIdx.x], red[threadIdx.x + s]);
        __syncthreads();
    }
    if (threadIdx.x == 0) atomicMax((int*)&d_scales[slot], __float_as_int(red[0]));
}

__device__ __forceinline__ int qlev(float w, float scale) {
    float r = rintf(w / scale);
    r = fminf(fmaxf(r, -128.f), 127.f);
    return (int)r;
}

// W1 -> dequantized fp32 (reference-identical per-element fl(q*s))
__global__ void quant_w1(const float* __restrict__ W1) {
    int i = blockIdx.x * blockDim.x + threadIdx.x;
    if (i >= H1_ * F_) return;
    float scale = d_scales[0] / 127.0f;
    d_Wq1[i] = (float)qlev(W1[i], scale) * scale;
}

// W2/Win/Wout/W3 -> packed int8
__global__ void pack_kernel(const float* __restrict__ W2, const float* __restrict__ Wi,
                            const float* __restrict__ Wo, const float* __restrict__ W3) {
    int i = blockIdx.x * blockDim.x + threadIdx.x;
    const int NW = H2_ * KW;
    const float* src; unsigned* dst; float mx; int local;
    if (i < NW)            { src = W2; dst = d_W2P; mx = d_scales[1]; local = i; }
    else if (i < 2 * NW)   { src = Wi; dst = d_WiP; mx = d_scales[2]; local = i - NW; }
    else if (i < 3 * NW)   { src = Wo; dst = d_WoP; mx = d_scales[3]; local = i - 2 * NW; }
    else if (i < 3 * NW + O_ * KW) { src = W3; dst = d_W3P; mx = d_scales[4]; local = i - 3 * NW; }
    else return;
    float scale = mx / 127.0f;
    float4 w = *(const float4*)(src + (size_t)local * 4);
    int q0 = qlev(w.x, scale), q1 = qlev(w.y, scale), q2 = qlev(w.z, scale), q3 = qlev(w.w, scale);
    dst[local] = (unsigned)(q0 & 0xFF) | ((unsigned)(q1 & 0xFF) << 8) |
                 ((unsigned)(q2 & 0xFF) << 16) | ((unsigned)(q3 & 0xFF) << 24);
}

// ---------------- first-layer GEMM via FFMA2, double-buffered (1 sync/iter) ----------------
// C[25600,512] = data @ Wq1.T. BM=128, BN=128, BK=16, 256 thr (8 warps).
// Per-output k-chain order identical to R6 (ascending k0, ascending kk) — bit-preserving.
__global__ void __launch_bounds__(256, 2) gemm_cur1_f2(const float* __restrict__ A) {
    __shared__ __align__(16) float As[2][16][128];
    __shared__ __align__(16) float Bs[2][16][128];
    const int tid = threadIdx.x;
    const int warp = tid >> 5, tx = tid & 31;
    const int m0 = blockIdx.y * 128, n0 = blockIdx.x * 128;
    const int lr = tid >> 1;            // 0..127
    const int lk = (tid & 1) * 8;       // 0 or 8
    const float* Ap = A + (size_t)(m0 + lr) * F_ + lk;
    const float* Wp = d_Wq1 + (size_t)(n0 + lr) * F_ + lk;

    unsigned long long acc[16][2];
#pragma unroll
    for (int i = 0; i < 16; i++) { acc[i][0] = 0ull; acc[i][1] = 0ull; }

    float4 a0 = *(const float4*)(Ap);
    float4 a1 = *(const float4*)(Ap + 4);
    float4 w0 = *(const float4*)(Wp);
    float4 w1 = *(const float4*)(Wp + 4);

    for (int kb = 0; kb < F_ / 16; kb++) {
        const int buf = kb & 1;
        As[buf][lk + 0][lr] = a0.x; As[buf][lk + 1][lr] = a0.y;
        As[buf][lk + 2][lr] = a0.z; As[buf][lk + 3][lr] = a0.w;
        As[buf][lk + 4][lr] = a1.x; As[buf][lk + 5][lr] = a1.y;
        As[buf][lk + 6][lr] = a1.z; As[buf][lk + 7][lr] = a1.w;
        Bs[buf][lk + 0][lr] = w0.x; Bs[buf][lk + 1][lr] = w0.y;
        Bs[buf][lk + 2][lr] = w0.z; Bs[buf][lk + 3][lr] = w0.w;
        Bs[buf][lk + 4][lr] = w1.x; Bs[buf][lk + 5][lr] = w1.y;
        Bs[buf][lk + 6][lr] = w1.z; Bs[buf][lk + 7][lr] = w1.w;
        __syncthreads();
        if (kb < F_ / 16 - 1) {
            int k0 = (kb + 1) * 16;
            a0 = *(const float4*)(Ap + k0);
            a1 = *(const float4*)(Ap + k0 + 4);
            w0 = *(const float4*)(Wp + k0);
            w1 = *(const float4*)(Wp + k0 + 4);
        }
#pragma unroll
        for (int kk = 0; kk < 16; kk++) {
            float4 b4 = *(const float4*)&Bs[buf][kk][tx * 4];
            unsigned long long bp0 = pk2(b4.x, b4.y);
            unsigned long long bp1 = pk2(b4.z, b4.w);
#pragma unroll
            for (int half = 0; half < 2; half++) {
                float4 x0 = *(const float4*)&As[buf][kk][warp * 16 + half * 8];
                float4 x1 = *(const float4*)&As[buf][kk][warp * 16 + half * 8 + 4];
                unsigned long long aa[8];
                aa[0] = pk2(x0.x, x0.x); aa[1] = pk2(x0.y, x0.y);
                aa[2] = pk2(x0.z, x0.z); aa[3] = pk2(x0.w, x0.w);
                aa[4] = pk2(x1.x, x1.x); aa[5] = pk2(x1.y, x1.y);
                aa[6] = pk2(x1.z, x1.z); aa[7] = pk2(x1.w, x1.w);
#pragma unroll
                for (int i = 0; i < 8; i++) {
                    ffma2(acc[half * 8 + i][0], aa[i], bp0);
                    ffma2(acc[half * 8 + i][1], aa[i], bp1);
                }
            }
        }
    }
#pragma unroll
    for (int i = 0; i < 16; i++) {
        size_t row = (size_t)(m0 + warp * 16 + i) * H1_ + n0 + tx * 4;
        float e0, e1, e2, e3;
        upk2(e0, e1, acc[i][0]);
        upk2(e2, e3, acc[i][1]);
        *(float2*)&d_cur1[row]     = make_float2(e0, e1);
        *(float2*)&d_cur1[row + 2] = make_float2(e2, e3);
    }
}

// ---------------- int8 tile GEMM: A tile 16 rows in sS, B (weights) 64 rows in uW ----------------
// ni MUST be 0..7 (rowB <= 63).
__device__ __forceinline__ void tile_mma_s8(int (&acc)[4], unsigned uS, unsigned uW,
                                            int ni, int lane) {
    const int rowA = lane & 15;
    const int rowB = ni * 8 + (lane & 7);       // ni 0..7 -> rows 0..63
    const unsigned aBase = uS + rowA * 512;
    const unsigned bBase = uW + rowB * 512;
    const int axor = rowA & 7, bxor = rowB & 7;
#pragma unroll
    for (int ki = 0; ki < 16; ki++) {
        unsigned aF[4], bF[2];
        ldmA(aF, aBase + (unsigned)((2 * ki + (lane >> 4)) ^ axor) * 16);
        ldmB(bF, bBase + (unsigned)((2 * ki + ((lane >> 3) & 1)) ^ bxor) * 16);
        mma_s8(acc, aF, bF);
    }
}

// smem word layout (dynamic):
//   sWi [0, 8192)  sW2 [8192, 16384)  sWo [16384, 24576)
//   sS  [24576, 26624)   sS2 [26624, 28672)   sW3 [28672, 29952)
#define SMEM_WORDS 29952
#define SMEM_BYTES (SMEM_WORDS * 4)

extern __shared__ __align__(16) unsigned smemRaw[];

// ---------------- persistent recurrent loop: grid (8,16), cluster (8,1,1), 256 thr ----------------
// Each cluster owns a 16-batch slice; CTA owns 64 h-columns x 16 batches; 8 warps (ni=warp).
__global__ void __launch_bounds__(256, 1) __cluster_dims__(8, 1, 1)
loop_kernel(float* __restrict__ out,
        const float* __restrict__ p_b1, const float* __restrict__ p_br,
        const float* __restrict__ p_bb, const float* __restrict__ p_bo,
        const float* __restrict__ p_vi, const float* __restrict__ p_vr,
        const float* __restrict__ p_vb, const float* __restrict__ p_vo) {
    unsigned* sWi = smemRaw;
    unsigned* sW2 = smemRaw + 8192;
    unsigned* sWo = smemRaw + 16384;
    unsigned* sS  = smemRaw + 24576;
    unsigned* sS2 = smemRaw + 26624;
    unsigned* sW3 = smemRaw + 28672;

    const int tid = threadIdx.x;
    const int bx = blockIdx.x;        // h-tile (64 h)
    const int by = blockIdx.y;        // batch slice (16 b)
    const int warp = tid >> 5, lane = tid & 31;
    const int ni = warp;              // 0..7: 8-col h tile within 64

    // stage weight tiles once (block owns h rows bx*64 .. +63)
    {
        const unsigned* wi = d_WiP + bx * 64 * KW;
        const unsigned* w2 = d_W2P + bx * 64 * KW;
        const unsigned* wo = d_WoP + bx * 64 * KW;
#pragma unroll
        for (int p = 0; p < 32; p++) {
            int idx = tid + p * 256;
            int r = idx >> 7, c = idx & 127;
            int d = r * 128 + ((((c >> 2) ^ (r & 7)) << 2) | (c & 3));
            sWi[d] = __ldg(wi + idx);
            sW2[d] = __ldg(w2 + idx);
            sWo[d] = __ldg(wo + idx);
        }
        for (int p = tid; p < O_ * KW; p += 256) sW3[p] = __ldg(d_W3P + p);
    }

    const float b1 = fminf(fmaxf(*p_b1, 0.f), 1.f);
    const float br = fminf(fmaxf(*p_br, 0.f), 1.f);
    const float bb = fminf(fmaxf(*p_bb, 0.f), 1.f);
    const float bo = fminf(fmaxf(*p_bo, 0.f), 1.f);
    const float vi = *p_vi, vr = *p_vr, vb = *p_vb, vo = *p_vo;
    const float s2f = d_scales[1] / 127.f;
    const float sif = d_scales[2] / 127.f;
    const float sof = d_scales[3] / 127.f;
    const float s3f = d_scales[4] / 127.f;

    const unsigned uWi = smem_u32(sWi), uW2 = smem_u32(sW2), uWo = smem_u32(sWo);
    const unsigned uSS = smem_u32(sS),  uS2 = smem_u32(sS2);

    // per-thread output coords (fixed across t): 16 batches x 64 h, 4 outputs/thread
    const int bl0 = lane >> 2;                        // local batch row, +8 for e2/e3
    const int hl0 = ni * 8 + (lane & 3) * 2;          // local h col (even), +1
    const int bg0 = by * 16 + bl0;                    // global batch
    const int hg0 = bx * 64 + hl0;                    // global h

    // membranes live in registers
    float m1v[4] = {0.f, 0.f, 0.f, 0.f};
    float bmv[4] = {0.f, 0.f, 0.f, 0.f};
    float rmv[4] = {0.f, 0.f, 0.f, 0.f};
    float m2v[3] = {0.f, 0.f, 0.f};

    unsigned short* s1S = (unsigned short*)d_s1P;
    unsigned short* bsS = (unsigned short*)d_bsP;
    unsigned short* rsS = (unsigned short*)d_rspkP;

    // prefetch cur1 for t = 0
    float curv[4];
    {
        float2 c0 = *(const float2*)&d_cur1[((size_t)bg0 * T_) * H1_ + hg0];
        float2 c1 = *(const float2*)&d_cur1[((size_t)(bg0 + 8) * T_) * H1_ + hg0];
        curv[0] = c0.x; curv[1] = c0.y; curv[2] = c1.x; curv[3] = c1.y;
    }

    const unsigned* rspkSrc = d_rspkP + by * 16 * KW;
    const unsigned* s1Src   = d_s1P  + by * 16 * KW;
    const unsigned* bsSrc   = d_bsP  + by * 16 * KW;

    for (int t = 0; t < T_; t++) {
        // ======== phase A ========
#pragma unroll
        for (int p = 0; p < 8; p++) {
            int idx = tid + p * 256;
            int r = idx >> 7, c = idx & 127;
            sS[r * 128 + ((((c >> 2) ^ (r & 7)) << 2) | (c & 3))] = __ldcg(rspkSrc + idx);
        }
        __syncthreads();

        int accA[4] = {0, 0, 0, 0};
        tile_mma_s8(accA, uSS, uWi, ni, lane);

        // output GEMV for t-1 from staged rspk (batches bx*2, bx*2+1 of this slice)
        if (t > 0) {
            int k = 0;
            for (int p = warp; p < 20; p += 8, k++) {
                int bl = bx * 2 + p / 10;
                int o = p % 10;
                uint4 sv = *(const uint4*)&sS[bl * 128 + ((lane ^ (bl & 7)) << 2)];
                uint4 wv = *(const uint4*)&sW3[o * 128 + lane * 4];
                int acc = 0;
                acc = __dp4a((int)sv.x, (int)wv.x, acc);
                acc = __dp4a((int)sv.y, (int)wv.y, acc);
                acc = __dp4a((int)sv.z, (int)wv.z, acc);
                acc = __dp4a((int)sv.w, (int)wv.w, acc);
#pragma unroll
                for (int off = 16; off; off >>= 1) acc += __shfl_xor_sync(0xffffffffu, acc, off);
                float m = bo * m2v[k] + s3f * (float)acc;
                int sp2 = m > vo;
                m2v[k] = sp2 ? 0.f : m;
                if (lane == 0)
                    out[((size_t)(t - 1) * B_ + (by * 16 + bl)) * O_ + o] = sp2 ? 1.f : 0.f;
            }
        }

        // phase A epilogue (register membranes; expressions identical to R6)
        int s1b[4], bsb[4];
#pragma unroll
        for (int e = 0; e < 4; e++) {
            float bm = bb * bmv[e] + sif * (float)accA[e];
            int bsp = bm > vb;
            bmv[e] = bsp ? 0.f : bm;
            bsb[e] = bsp;
            float mm = b1 * m1v[e] + curv[e];
            int s1i = mm > vi;
            m1v[e] = s1i ? 0.f : mm;
            s1b[e] = s1i;
        }
        {
            size_t i0 = ((size_t)bg0 * H2_ + hg0) >> 1;
            size_t i1 = ((size_t)(bg0 + 8) * H2_ + hg0) >> 1;
            s1S[i0] = (unsigned short)(s1b[0] | (s1b[1] << 8));
            s1S[i1] = (unsigned short)(s1b[2] | (s1b[3] << 8));
            bsS[i0] = (unsigned short)(bsb[0] | (bsb[1] << 8));
            bsS[i1] = (unsigned short)(bsb[2] | (bsb[3] << 8));
        }
        // prefetch cur1 for t+1 (overlaps phase B)
        if (t + 1 < T_) {
            float2 c0 = *(const float2*)&d_cur1[((size_t)bg0 * T_ + t + 1) * H1_ + hg0];
            float2 c1 = *(const float2*)&d_cur1[((size_t)(bg0 + 8) * T_ + t + 1) * H1_ + hg0];
            curv[0] = c0.x; curv[1] = c0.y; curv[2] = c1.x; curv[3] = c1.y;
        }
        CLUSYNC();

        // ======== phase B: rmem = br*rmem + s1@Wq2.T + bs@Wqo.T ========
#pragma unroll
        for (int p = 0; p < 8; p++) {
            int idx = tid + p * 256;
            int r = idx >> 7, c = idx & 127;
            int d = r * 128 + ((((c >> 2) ^ (r & 7)) << 2) | (c & 3));
            sS[d]  = __ldcg(s1Src + idx);
            sS2[d] = __ldcg(bsSrc + idx);
        }
        __syncthreads();

        int acc1[4] = {0, 0, 0, 0};
        int acc2[4] = {0, 0, 0, 0};
        tile_mma_s8(acc1, uSS, uW2, ni, lane);
        tile_mma_s8(acc2, uS2, uWo, ni, lane);

        int rsb[4];
#pragma unroll
        for (int e = 0; e < 4; e++) {
            float cur = s2f * (float)acc1[e];
            cur += sof * (float)acc2[e];
            float rm = br * rmv[e] + cur;
            int rsp = rm > vr;
            rmv[e] = rsp ? 0.f : rm;
            rsb[e] = rsp;
        }
        {
            size_t i0 = ((size_t)bg0 * H2_ + hg0) >> 1;
            size_t i1 = ((size_t)(bg0 + 8) * H2_ + hg0) >> 1;
            rsS[i0] = (unsigned short)(rsb[0] | (rsb[1] << 8));
            rsS[i1] = (unsigned short)(rsb[2] | (rsb[3] << 8));
        }
        CLUSYNC();
    }

    // ======== final output GEMV for t = T-1 ========
#pragma unroll
    for (int p = 0; p < 8; p++) {
        int idx = tid + p * 256;
        int r = idx >> 7, c = idx & 127;
        sS[r * 128 + ((((c >> 2) ^ (r & 7)) << 2) | (c & 3))] = __ldcg(rspkSrc + idx);
    }
    __syncthreads();
    {
        int k = 0;
        for (int p = warp; p < 20; p += 8, k++) {
            int bl = bx * 2 + p / 10;
            int o = p % 10;
            uint4 sv = *(const uint4*)&sS[bl * 128 + ((lane ^ (bl & 7)) << 2)];
            uint4 wv = *(const uint4*)&sW3[o * 128 + lane * 4];
            int acc = 0;
            acc = __dp4a((int)sv.x, (int)wv.x, acc);
            acc = __dp4a((int)sv.y, (int)wv.y, acc);
            acc = __dp4a((int)sv.z, (int)wv.z, acc);
            acc = __dp4a((int)sv.w, (int)wv.w, acc);
#pragma unroll
            for (int off = 16; off; off >>= 1) acc += __shfl_xor_sync(0xffffffffu, acc, off);
            float m = bo * m2v[k] + s3f * (float)acc;
            int sp2 = m > vo;
            if (lane == 0)
                out[((size_t)(T_ - 1) * B_ + (by * 16 + bl)) * O_ + o] = sp2 ? 1.f : 0.f;
        }
    }
}

// ---------------- launch ----------------
extern "C" void kernel_launch(void* const* d_in, const int* in_sizes, int n_in,
                              void* d_out, int out_size) {
    const float* data = (const float*)d_in[0];
    const float* W1   = (const float*)d_in[1];
    const float* W2   = (const float*)d_in[2];
    const float* Win  = (const float*)d_in[3];
    const float* Wout = (const float*)d_in[4];
    const float* W3   = (const float*)d_in[5];
    const float* beta_in   = (const float*)d_in[6];
    const float* beta_rec  = (const float*)d_in[7];
    const float* beta_back = (const float*)d_in[8];
    const float* beta_out  = (const float*)d_in[9];
    const float* vth_in    = (const float*)d_in[10];
    const float* vth_rec   = (const float*)d_in[11];
    const float* vth_back  = (const float*)d_in[12];
    const float* vth_out   = (const float*)d_in[13];
    float* out = (float*)d_out;

    cudaFuncSetAttribute(loop_kernel, cudaFuncAttributeMaxDynamicSharedMemorySize, SMEM_BYTES);

    init_kernel<<<(B_ * KW + 255) / 256, 256>>>();

    maxabs_all<<<dim3(64, 5), 256>>>(W1, W2, Win, Wout, W3);

    quant_w1<<<(H1_ * F_ + 255) / 256, 256>>>(W1);
    int nwords = 3 * H2_ * KW + O_ * KW;
    pack_kernel<<<(nwords + 255) / 256, 256>>>(W2, Win, Wout, W3);

    gemm_cur1_f2<<<dim3(H1_ / 128, (B_ * T_) / 128), 256>>>(data);

    loop_kernel<<<dim3(8, 16), 256, SMEM_BYTES>>>(out, beta_in, beta_rec, beta_back, beta_out,
                                                  vth_in, vth_rec, vth_back, vth_out);
}

// round 13
// speedup vs baseline: 1.1832x; 1.1832x over previous
#include <cuda_runtime.h>
#include <math.h>

#define B_  256
#define T_  100
#define F_  1024
#define H1_ 512
#define H2_ 512
#define O_  10
#define KW  128          // u32 words per 512-int8 row

// ---------------- device scratch ----------------
__device__ float d_Wq1[H1_ * F_];                 // dequantized fp32 W1
__device__ unsigned d_W2P[H2_ * KW];              // packed int8 q
__device__ unsigned d_WiP[H2_ * KW];
__device__ unsigned d_WoP[H2_ * KW];
__device__ unsigned d_W3P[O_ * KW];               // 1280 words
__device__ float d_cur1[(size_t)T_ * B_ * H1_];   // T-MAJOR: [(t*B + b), h1]
__device__ unsigned d_s1P[B_ * KW];               // spikes packed as bytes
__device__ unsigned d_bsP[B_ * KW];
__device__ unsigned d_rspkP[B_ * KW];
__device__ float d_scales[5];
__device__ int d_done[T_];                        // gemm progress: 8 blocks per t

// ---------------- asm wrappers ----------------
__device__ __forceinline__ unsigned smem_u32(const void* p) {
    return (unsigned)__cvta_generic_to_shared(p);
}
__device__ __forceinline__ void ldmA(unsigned (&a)[4], unsigned addr) {
    asm volatile("ldmatrix.sync.aligned.m8n8.x4.shared.b16 {%0,%1,%2,%3}, [%4];"
                 : "=r"(a[0]), "=r"(a[1]), "=r"(a[2]), "=r"(a[3]) : "r"(addr));
}
__device__ __forceinline__ void ldmB(unsigned (&b)[2], unsigned addr) {
    asm volatile("ldmatrix.sync.aligned.m8n8.x2.shared.b16 {%0,%1}, [%2];"
                 : "=r"(b[0]), "=r"(b[1]) : "r"(addr));
}
__device__ __forceinline__ void mma_s8(int (&c)[4], const unsigned (&a)[4], const unsigned (&b)[2]) {
    asm volatile("mma.sync.aligned.m16n8k32.row.col.s32.s8.s8.s32 "
                 "{%0,%1,%2,%3},{%4,%5,%6,%7},{%8,%9},{%0,%1,%2,%3};"
                 : "+r"(c[0]), "+r"(c[1]), "+r"(c[2]), "+r"(c[3])
                 : "r"(a[0]), "r"(a[1]), "r"(a[2]), "r"(a[3]), "r"(b[0]), "r"(b[1]));
}
// packed fp32x2 FMA (per-lane IEEE fp32 fma; proven rel_err-neutral R4/R6/R12)
__device__ __forceinline__ void ffma2(unsigned long long &c, unsigned long long a, unsigned long long b) {
    asm("fma.rn.f32x2 %0, %1, %2, %0;" : "+l"(c) : "l"(a), "l"(b));
}
__device__ __forceinline__ unsigned long long pk2(float x, float y) {
    unsigned long long r;
    asm("mov.b64 %0, {%1, %2};" : "=l"(r) : "f"(x), "f"(y));
    return r;
}
__device__ __forceinline__ void upk2(float &x, float &y, unsigned long long v) {
    asm("mov.b64 {%0, %1}, %2;" : "=f"(x), "=f"(y) : "l"(v));
}
#define CLUSYNC() do { \
    asm volatile("barrier.cluster.arrive.aligned;" ::: "memory"); \
    asm volatile("barrier.cluster.wait.aligned;"   ::: "memory"); \
} while (0)

__device__ __forceinline__ void wait_done(int t) {
    volatile int* vd = d_done;
    while (vd[t] < 8) __nanosleep(128);
}

// ---------------- init ----------------
__global__ void init_kernel() {
    int i = blockIdx.x * blockDim.x + threadIdx.x;
    if (i < B_ * KW) d_rspkP[i] = 0u;
    if (i < 5) d_scales[i] = 0.f;
    if (i < T_) d_done[i] = 0;
}

// ---------------- max|w| for all 5 matrices, one launch ----------------
__global__ void maxabs_all(const float* __restrict__ W1, const float* __restrict__ W2,
                           const float* __restrict__ Wi, const float* __restrict__ Wo,
                           const float* __restrict__ W3) {
    __shared__ float red[256];
    int slot = blockIdx.y;
    const float* w; int n;
    switch (slot) {
        case 0: w = W1; n = H1_ * F_;  break;
        case 1: w = W2; n = H2_ * H1_; break;
        case 2: w = Wi; n = H2_ * H2_; break;
        case 3: w = Wo; n = H2_ * H2_; break;
        default: w = W3; n = O_ * H2_; break;
    }
    float m = 0.f;
    for (int i = blockIdx.x * blockDim.x + threadIdx.x; i < n; i += gridDim.x * blockDim.x)
        m = fmaxf(m, fabsf(w[i]));
    red[threadIdx.x] = m;
    __syncthreads();
    for (int s = 128; s > 0; s >>= 1) {
        if (threadIdx.x < s) red[threadIdx.x] = fmaxf(red[threadIdx.x], red[threadIdx.x + s]);
        __syncthreads();
    }
    if (threadIdx.x == 0) atomicMax((int*)&d_scales[slot], __float_as_int(red[0]));
}

__device__ __forceinline__ int qlev(float w, float scale) {
    float r = rintf(w / scale);
    r = fminf(fmaxf(r, -128.f), 127.f);
    return (int)r;
}

// W1 -> dequantized fp32 (reference-identical per-element fl(q*s))
__global__ void quant_w1(const float* __restrict__ W1) {
    int i = blockIdx.x * blockDim.x + threadIdx.x;
    if (i >= H1_ * F_) return;
    float scale = d_scales[0] / 127.0f;
    d_Wq1[i] = (float)qlev(W1[i], scale) * scale;
}

// W2/Win/Wout/W3 -> packed int8
__global__ void pack_kernel(const float* __restrict__ W2, const float* __restrict__ Wi,
                            const float* __restrict__ Wo, const float* __restrict__ W3) {
    int i = blockIdx.x * blockDim.x + threadIdx.x;
    const int NW = H2_ * KW;
    const float* src; unsigned* dst; float mx; int local;
    if (i < NW)            { src = W2; dst = d_W2P; mx = d_scales[1]; local = i; }
    else if (i < 2 * NW)   { src = Wi; dst = d_WiP; mx = d_scales[2]; local = i - NW; }
    else if (i < 3 * NW)   { src = Wo; dst = d_WoP; mx = d_scales[3]; local = i - 2 * NW; }
    else if (i < 3 * NW + O_ * KW) { src = W3; dst = d_W3P; mx = d_scales[4]; local = i - 3 * NW; }
    else return;
    float scale = mx / 127.0f;
    float4 w = *(const float4*)(src + (size_t)local * 4);
    int q0 = qlev(w.x, scale), q1 = qlev(w.y, scale), q2 = qlev(w.z, scale), q3 = qlev(w.w, scale);
    dst[local] = (unsigned)(q0 & 0xFF) | ((unsigned)(q1 & 0xFF) << 8) |
                 ((unsigned)(q2 & 0xFF) << 16) | ((unsigned)(q3 & 0xFF) << 24);
}

// ---------------- first-layer GEMM via FFMA2, double-buffered, t-major output ----------------
// One block = (t, b-half 128 rows, 128 n-cols). grid (4, 200): y = t*2 + half (ascending t).
// Per-output k-chain order identical to R6/R12 — bit-preserving.
__global__ void __launch_bounds__(256, 2) gemm_cur1_f2(const float* __restrict__ A) {
    __shared__ __align__(16) float As[2][16][128];
    __shared__ __align__(16) float Bs[2][16][128];
    const int tid = threadIdx.x;
    const int warp = tid >> 5, tx = tid & 31;
    const int t = blockIdx.y >> 1;
    const int bbase = (blockIdx.y & 1) * 128;
    const int n0 = blockIdx.x * 128;
    const int lr = tid >> 1;            // 0..127
    const int lk = (tid & 1) * 8;       // 0 or 8
    const float* Ap = A + ((size_t)(bbase + lr) * T_ + t) * F_ + lk;
    const float* Wp = d_Wq1 + (size_t)(n0 + lr) * F_ + lk;

    unsigned long long acc[16][2];
#pragma unroll
    for (int i = 0; i < 16; i++) { acc[i][0] = 0ull; acc[i][1] = 0ull; }

    float4 a0 = *(const float4*)(Ap);
    float4 a1 = *(const float4*)(Ap + 4);
    float4 w0 = *(const float4*)(Wp);
    float4 w1 = *(const float4*)(Wp + 4);

    for (int kb = 0; kb < F_ / 16; kb++) {
        const int buf = kb & 1;
        As[buf][lk + 0][lr] = a0.x; As[buf][lk + 1][lr] = a0.y;
        As[buf][lk + 2][lr] = a0.z; As[buf][lk + 3][lr] = a0.w;
        As[buf][lk + 4][lr] = a1.x; As[buf][lk + 5][lr] = a1.y;
        As[buf][lk + 6][lr] = a1.z; As[buf][lk + 7][lr] = a1.w;
        Bs[buf][lk + 0][lr] = w0.x; Bs[buf][lk + 1][lr] = w0.y;
        Bs[buf][lk + 2][lr] = w0.z; Bs[buf][lk + 3][lr] = w0.w;
        Bs[buf][lk + 4][lr] = w1.x; Bs[buf][lk + 5][lr] = w1.y;
        Bs[buf][lk + 6][lr] = w1.z; Bs[buf][lk + 7][lr] = w1.w;
        __syncthreads();
        if (kb < F_ / 16 - 1) {
            int k0 = (kb + 1) * 16;
            a0 = *(const float4*)(Ap + k0);
            a1 = *(const float4*)(Ap + k0 + 4);
            w0 = *(const float4*)(Wp + k0);
            w1 = *(const float4*)(Wp + k0 + 4);
        }
#pragma unroll
        for (int kk = 0; kk < 16; kk++) {
            float4 b4 = *(const float4*)&Bs[buf][kk][tx * 4];
            unsigned long long bp0 = pk2(b4.x, b4.y);
            unsigned long long bp1 = pk2(b4.z, b4.w);
#pragma unroll
            for (int half = 0; half < 2; half++) {
                float4 x0 = *(const float4*)&As[buf][kk][warp * 16 + half * 8];
                float4 x1 = *(const float4*)&As[buf][kk][warp * 16 + half * 8 + 4];
                unsigned long long aa[8];
                aa[0] = pk2(x0.x, x0.x); aa[1] = pk2(x0.y, x0.y);
                aa[2] = pk2(x0.z, x0.z); aa[3] = pk2(x0.w, x0.w);
                aa[4] = pk2(x1.x, x1.x); aa[5] = pk2(x1.y, x1.y);
                aa[6] = pk2(x1.z, x1.z); aa[7] = pk2(x1.w, x1.w);
#pragma unroll
                for (int i = 0; i < 8; i++) {
                    ffma2(acc[half * 8 + i][0], aa[i], bp0);
                    ffma2(acc[half * 8 + i][1], aa[i], bp1);
                }
            }
        }
    }
#pragma unroll
    for (int i = 0; i < 16; i++) {
        size_t row = ((size_t)t * B_ + bbase + warp * 16 + i) * H1_ + n0 + tx * 4;
        float e0, e1, e2, e3;
        upk2(e0, e1, acc[i][0]);
        upk2(e2, e3, acc[i][1]);
        *(float2*)&d_cur1[row]     = make_float2(e0, e1);
        *(float2*)&d_cur1[row + 2] = make_float2(e2, e3);
    }
    // publish progress: 8 blocks per t
    __threadfence();
    __syncthreads();
    if (tid == 0) atomicAdd(&d_done[t], 1);
}

// ---------------- int8 tile GEMM: A tile 32 rows in sS, B (weights) 64 rows in uW ----------------
__device__ __forceinline__ void tile_mma_s8(int (&acc)[4], unsigned uS, unsigned uW,
                                            int mi, int ni, int lane) {
    const int rowA = mi * 16 + (lane & 15);
    const int rowB = ni * 8 + (lane & 7);
    const unsigned aBase = uS + rowA * 512;
    const unsigned bBase = uW + rowB * 512;
    const int axor = rowA & 7, bxor = rowB & 7;
#pragma unroll
    for (int ki = 0; ki < 16; ki++) {
        unsigned aF[4], bF[2];
        ldmA(aF, aBase + (unsigned)((2 * ki + (lane >> 4)) ^ axor) * 16);
        ldmB(bF, bBase + (unsigned)((2 * ki + ((lane >> 3) & 1)) ^ bxor) * 16);
        mma_s8(acc, aF, bF);
    }
}

// smem word layout (dynamic):
//   sWi [0, 8192)  sW2 [8192, 16384)  sWo [16384, 24576)
//   sS  [24576, 28672)   sS2 [28672, 32768)   sW3 [32768, 34048)
#define SMEM_WORDS 34048
#define SMEM_BYTES (SMEM_WORDS * 4)

extern __shared__ __align__(16) unsigned smemRaw[];

// ---------------- persistent recurrent loop: grid (8,8), cluster (8,1,1), 512 thr (R6) ----------------
__global__ void __launch_bounds__(512, 1) __cluster_dims__(8, 1, 1)
loop_kernel(float* __restrict__ out,
        const float* __restrict__ p_b1, const float* __restrict__ p_br,
        const float* __restrict__ p_bb, const float* __restrict__ p_bo,
        const float* __restrict__ p_vi, const float* __restrict__ p_vr,
        const float* __restrict__ p_vb, const float* __restrict__ p_vo) {
    unsigned* sWi = smemRaw;
    unsigned* sW2 = smemRaw + 8192;
    unsigned* sWo = smemRaw + 16384;
    unsigned* sS  = smemRaw + 24576;
    unsigned* sS2 = smemRaw + 28672;
    unsigned* sW3 = smemRaw + 32768;

    const int tid = threadIdx.x;
    const int bx = blockIdx.x;
    const int by = blockIdx.y;
    const int warp = tid >> 5, lane = tid & 31;
    const int mi = warp & 1;
    const int ni = warp >> 1;

    {
        const unsigned* wi = d_WiP + bx * 64 * KW;
        const unsigned* w2 = d_W2P + bx * 64 * KW;
        const unsigned* wo = d_WoP + bx * 64 * KW;
#pragma unroll
        for (int p = 0; p < 16; p++) {
            int idx = tid + p * 512;
            int r = idx >> 7, c = idx & 127;
            int d = r * 128 + ((((c >> 2) ^ (r & 7)) << 2) | (c & 3));
            sWi[d] = __ldg(wi + idx);
            sW2[d] = __ldg(w2 + idx);
            sWo[d] = __ldg(wo + idx);
        }
        for (int p = tid; p < O_ * KW; p += 512) sW3[p] = __ldg(d_W3P + p);
    }

    const float b1 = fminf(fmaxf(*p_b1, 0.f), 1.f);
    const float br = fminf(fmaxf(*p_br, 0.f), 1.f);
    const float bb = fminf(fmaxf(*p_bb, 0.f), 1.f);
    const float bo = fminf(fmaxf(*p_bo, 0.f), 1.f);
    const float vi = *p_vi, vr = *p_vr, vb = *p_vb, vo = *p_vo;
    const float s2f = d_scales[1] / 127.f;
    const float sif = d_scales[2] / 127.f;
    const float sof = d_scales[3] / 127.f;
    const float s3f = d_scales[4] / 127.f;

    const unsigned uWi = smem_u32(sWi), uW2 = smem_u32(sW2), uWo = smem_u32(sWo);
    const unsigned uSS = smem_u32(sS),  uS2 = smem_u32(sS2);

    const int bl0 = mi * 16 + (lane >> 2);
    const int hl0 = ni * 8 + (lane & 3) * 2;
    const int bg0 = by * 32 + bl0;
    const int hg0 = bx * 64 + hl0;

    float m1v[4] = {0.f, 0.f, 0.f, 0.f};
    float bmv[4] = {0.f, 0.f, 0.f, 0.f};
    float rmv[4] = {0.f, 0.f, 0.f, 0.f};
    float m2v[3] = {0.f, 0.f, 0.f};

    unsigned short* s1S = (unsigned short*)d_s1P;
    unsigned short* bsS = (unsigned short*)d_bsP;
    unsigned short* rsS = (unsigned short*)d_rspkP;

    // wait for gemm to finish t=0, then prefetch cur1 (t-major)
    wait_done(0);
    float curv[4];
    {
        float2 c0 = *(const float2*)&d_cur1[((size_t)0 * B_ + bg0) * H1_ + hg0];
        float2 c1 = *(const float2*)&d_cur1[((size_t)0 * B_ + bg0 + 8) * H1_ + hg0];
        curv[0] = c0.x; curv[1] = c0.y; curv[2] = c1.x; curv[3] = c1.y;
    }

    const unsigned* rspkSrc = d_rspkP + by * 32 * KW;
    const unsigned* s1Src   = d_s1P  + by * 32 * KW;
    const unsigned* bsSrc   = d_bsP  + by * 32 * KW;

    for (int t = 0; t < T_; t++) {
        // ======== phase A ========
#pragma unroll
        for (int p = 0; p < 8; p++) {
            int idx = tid + p * 512;
            int r = idx >> 7, c = idx & 127;
            sS[r * 128 + ((((c >> 2) ^ (r & 7)) << 2) | (c & 3))] = __ldcg(rspkSrc + idx);
        }
        __syncthreads();

        int accA[4] = {0, 0, 0, 0};
        tile_mma_s8(accA, uSS, uWi, mi, ni, lane);

        if (t > 0) {
            int k = 0;
            for (int p = warp; p < 40; p += 16, k++) {
                int bl = bx * 4 + p / 10;
                int o = p % 10;
                uint4 sv = *(const uint4*)&sS[bl * 128 + ((lane ^ (bl & 7)) << 2)];
                uint4 wv = *(const uint4*)&sW3[o * 128 + lane * 4];
                int acc = 0;
                acc = __dp4a((int)sv.x, (int)wv.x, acc);
                acc = __dp4a((int)sv.y, (int)wv.y, acc);
                acc = __dp4a((int)sv.z, (int)wv.z, acc);
                acc = __dp4a((int)sv.w, (int)wv.w, acc);
#pragma unroll
                for (int off = 16; off; off >>= 1) acc += __shfl_xor_sync(0xffffffffu, acc, off);
                float m = bo * m2v[k] + s3f * (float)acc;
                int sp2 = m > vo;
                m2v[k] = sp2 ? 0.f : m;
                if (lane == 0)
                    out[((size_t)(t - 1) * B_ + (by * 32 + bl)) * O_ + o] = sp2 ? 1.f : 0.f;
            }
        }

        int s1b[4], bsb[4];
#pragma unroll
        for (int e = 0; e < 4; e++) {
            float bm = bb * bmv[e] + sif * (float)accA[e];
            int bsp = bm > vb;
            bmv[e] = bsp ? 0.f : bm;
            bsb[e] = bsp;
            float mm = b1 * m1v[e] + curv[e];
            int s1i = mm > vi;
            m1v[e] = s1i ? 0.f : mm;
            s1b[e] = s1i;
        }
        {
            size_t i0 = ((size_t)bg0 * H2_ + hg0) >> 1;
            size_t i1 = ((size_t)(bg0 + 8) * H2_ + hg0) >> 1;
            s1S[i0] = (unsigned short)(s1b[0] | (s1b[1] << 8));
            s1S[i1] = (unsigned short)(s1b[2] | (s1b[3] << 8));
            bsS[i0] = (unsigned short)(bsb[0] | (bsb[1] << 8));
            bsS[i1] = (unsigned short)(bsb[2] | (bsb[3] << 8));
        }
        // wait + prefetch cur1 for t+1 (t-major; overlaps phase B)
        if (t + 1 < T_) {
            wait_done(t + 1);
            float2 c0 = *(const float2*)&d_cur1[((size_t)(t + 1) * B_ + bg0) * H1_ + hg0];
            float2 c1 = *(const float2*)&d_cur1[((size_t)(t + 1) * B_ + bg0 + 8) * H1_ + hg0];
            curv[0] = c0.x; curv[1] = c0.y; curv[2] = c1.x; curv[3] = c1.y;
        }
        CLUSYNC();

        // ======== phase B: rmem = br*rmem + s1@Wq2.T + bs@Wqo.T ========
#pragma unroll
        for (int p = 0; p < 8; p++) {
            int idx = tid + p * 512;
            int r = idx >> 7, c = idx & 127;
            int d = r * 128 + ((((c >> 2) ^ (r & 7)) << 2) | (c & 3));
            sS[d]  = __ldcg(s1Src + idx);
            sS2[d] = __ldcg(bsSrc + idx);
        }
        __syncthreads();

        int acc1[4] = {0, 0, 0, 0};
        int acc2[4] = {0, 0, 0, 0};
        tile_mma_s8(acc1, uSS, uW2, mi, ni, lane);
        tile_mma_s8(acc2, uS2, uWo, mi, ni, lane);

        int rsb[4];
#pragma unroll
        for (int e = 0; e < 4; e++) {
            float cur = s2f * (float)acc1[e];
            cur += sof * (float)acc2[e];
            float rm = br * rmv[e] + cur;
            int rsp = rm > vr;
            rmv[e] = rsp ? 0.f : rm;
            rsb[e] = rsp;
        }
        {
            size_t i0 = ((size_t)bg0 * H2_ + hg0) >> 1;
            size_t i1 = ((size_t)(bg0 + 8) * H2_ + hg0) >> 1;
            rsS[i0] = (unsigned short)(rsb[0] | (rsb[1] << 8));
            rsS[i1] = (unsigned short)(rsb[2] | (rsb[3] << 8));
        }
        CLUSYNC();
    }

    // ======== final output GEMV for t = T-1 ========
#pragma unroll
    for (int p = 0; p < 8; p++) {
        int idx = tid + p * 512;
        int r = idx >> 7, c = idx & 127;
        sS[r * 128 + ((((c >> 2) ^ (r & 7)) << 2) | (c & 3))] = __ldcg(rspkSrc + idx);
    }
    __syncthreads();
    {
        int k = 0;
        for (int p = warp; p < 40; p += 16, k++) {
            int bl = bx * 4 + p / 10;
            int o = p % 10;
            uint4 sv = *(const uint4*)&sS[bl * 128 + ((lane ^ (bl & 7)) << 2)];
            uint4 wv = *(const uint4*)&sW3[o * 128 + lane * 4];
            int acc = 0;
            acc = __dp4a((int)sv.x, (int)wv.x, acc);
            acc = __dp4a((int)sv.y, (int)wv.y, acc);
            acc = __dp4a((int)sv.z, (int)wv.z, acc);
            acc = __dp4a((int)sv.w, (int)wv.w, acc);
#pragma unroll
            for (int off = 16; off; off >>= 1) acc += __shfl_xor_sync(0xffffffffu, acc, off);
            float m = bo * m2v[k] + s3f * (float)acc;
            int sp2 = m > vo;
            if (lane == 0)
                out[((size_t)(T_ - 1) * B_ + (by * 32 + bl)) * O_ + o] = sp2 ? 1.f : 0.f;
        }
    }
}

// ---------------- launch: fork gemm onto a second stream, overlap with loop ----------------
extern "C" void kernel_launch(void* const* d_in, const int* in_sizes, int n_in,
                              void* d_out, int out_size) {
    const float* data = (const float*)d_in[0];
    const float* W1   = (const float*)d_in[1];
    const float* W2   = (const float*)d_in[2];
    const float* Win  = (const float*)d_in[3];
    const float* Wout = (const float*)d_in[4];
    const float* W3   = (const float*)d_in[5];
    const float* beta_in   = (const float*)d_in[6];
    const float* beta_rec  = (const float*)d_in[7];
    const float* beta_back = (const float*)d_in[8];
    const float* beta_out  = (const float*)d_in[9];
    const float* vth_in    = (const float*)d_in[10];
    const float* vth_rec   = (const float*)d_in[11];
    const float* vth_back  = (const float*)d_in[12];
    const float* vth_out   = (const float*)d_in[13];
    float* out = (float*)d_out;

    static cudaStream_t s2 = nullptr;
    static cudaEvent_t evFork = nullptr, evJoin = nullptr;
    if (s2 == nullptr) {   // created on the (uncaptured) correctness call; reused thereafter
        cudaStreamCreateWithFlags(&s2, cudaStreamNonBlocking);
        cudaEventCreateWithFlags(&evFork, cudaEventDisableTiming);
        cudaEventCreateWithFlags(&evJoin, cudaEventDisableTiming);
    }

    cudaFuncSetAttribute(loop_kernel, cudaFuncAttributeMaxDynamicSharedMemorySize, SMEM_BYTES);

    // prologue (default stream)
    init_kernel<<<(B_ * KW + 255) / 256, 256>>>();
    maxabs_all<<<dim3(64, 5), 256>>>(W1, W2, Win, Wout, W3);
    quant_w1<<<(H1_ * F_ + 255) / 256, 256>>>(W1);
    int nwords = 3 * H2_ * KW + O_ * KW;
    pack_kernel<<<(nwords + 255) / 256, 256>>>(W2, Win, Wout, W3);

    // fork: gemm runs on s2 concurrently with the loop on the default stream
    cudaEventRecord(evFork, 0);
    cudaStreamWaitEvent(s2, evFork, 0);
    gemm_cur1_f2<<<dim3(4, 2 * T_), 256, 0, s2>>>(data);
    cudaEventRecord(evJoin, s2);

    loop_kernel<<<dim3(8, 8), 512, SMEM_BYTES>>>(out, beta_in, beta_rec, beta_back, beta_out,
                                                 vth_in, vth_rec, vth_back, vth_out);

    // join: downstream work on the default stream waits for the gemm too
    cudaStreamWaitEvent(0, evJoin, 0);
}